// round 13
// baseline (speedup 1.0000x reference)
#include <cuda_runtime.h>
#include <cuda_fp16.h>
#include <cstdint>
#include <math.h>

#define PW 49
#define DD 128

// masked rel-pos bias, fp16, [4 heads][49 i][56 j] (j>=49 -> -60000)
__device__ __half g_bias[4 * 49 * 56];

__global__ void prep_bias_kernel(const float* __restrict__ table)
{
    int t = blockIdx.x * 256 + threadIdx.x;
    if (t >= 4 * 49 * 56) return;
    int h = t / (49 * 56);
    int rem = t - h * (49 * 56);
    int i = rem / 56, j = rem - i * 56;
    float v = -60000.0f;
    if (j < PW) {
        int ri = i / 7, ci = i - ri * 7;
        int rj = j / 7, cj = j - rj * 7;
        v = table[(((ri - rj + 6) * 13) + (ci - cj + 6)) * 4 + h];
    }
    g_bias[t] = __float2half_rn(v);
}

// ---------------- smem layout (halfs) ----------------
// wq  [128][392] : resident Wqkv fp16
// wm  [128][136] : resident Wmerge fp16
// buf[b] (b=0,1): Q rows 0..55 | K rows 56..111 | V rows 112..175, pitch 136.
//   V doubles as x staging; Q doubles as attn-out. Pad rows zeroed once,
//   all stores guarded row<49 so pads stay zero.
static constexpr int WQ_P = 392;
static constexpr int WM_P = 136;
static constexpr int BP   = 136;
static constexpr int WQ_OFF  = 0;
static constexpr int WM_OFF  = 128 * WQ_P;             // 50176
static constexpr int BUF_OFF = WM_OFF + 128 * WM_P;    // 67584
static constexpr int K_ROFF  = 56 * BP;
static constexpr int V_ROFF  = 112 * BP;
static constexpr int BUF_SZ  = 176 * BP;               // 23936
static constexpr int HALFS   = BUF_OFF + 2 * BUF_SZ;   // 115456
static constexpr int SMEM_BYTES = HALFS * 2;           // 230912

__device__ __forceinline__ uint32_t cvta_s(const void* p)
{
    return (uint32_t)__cvta_generic_to_shared(p);
}
__device__ __forceinline__ uint32_t f2h2(float a, float b)
{
    __half2 h = __floats2half2_rn(a, b);
    return *reinterpret_cast<uint32_t*>(&h);
}
__device__ __forceinline__ void gbar(int id)
{
    asm volatile("bar.sync %0, %1;" :: "r"(id), "r"(256) : "memory");
}

#define LDSM4(R0,R1,R2,R3,ADDR) \
    asm volatile("ldmatrix.sync.aligned.m8n8.x4.shared.b16 {%0,%1,%2,%3},[%4];" \
        : "=r"(R0),"=r"(R1),"=r"(R2),"=r"(R3) : "r"(ADDR))
#define LDSM4T(R0,R1,R2,R3,ADDR) \
    asm volatile("ldmatrix.sync.aligned.m8n8.x4.trans.shared.b16 {%0,%1,%2,%3},[%4];" \
        : "=r"(R0),"=r"(R1),"=r"(R2),"=r"(R3) : "r"(ADDR))
#define MMA(C0,C1,C2,C3,A0,A1,A2,A3,B0,B1) \
    asm volatile("mma.sync.aligned.m16n8k16.row.col.f32.f16.f16.f32 " \
        "{%0,%1,%2,%3},{%4,%5,%6,%7},{%8,%9},{%0,%1,%2,%3};" \
        : "+f"(C0),"+f"(C1),"+f"(C2),"+f"(C3) \
        : "r"(A0),"r"(A1),"r"(A2),"r"(A3),"r"(B0),"r"(B1))

__global__ void __launch_bounds__(512, 1)
rpmha_ws_kernel(const float* __restrict__ x,
                const float* __restrict__ Wqkv,
                const float* __restrict__ bqkv,
                const float* __restrict__ Wmerge,
                const float* __restrict__ bmerge,
                float* __restrict__ out, int nwin)
{
    extern __shared__ __half sh[];
    __half* wq = sh + WQ_OFF;
    __half* wm = sh + WM_OFF;

    const int tid = threadIdx.x, warp = tid >> 5, lane = tid & 31;
    const bool isGemm = (warp < 8);    // warps 0-7: QKV GEMM; 8-15: attn+merge
    const int lw   = warp & 7;
    const int gtid = tid & 255;

    const uint32_t wq_s = cvta_s(wq);
    const uint32_t wm_s = cvta_s(wm);
    const float scale = 0.17677669529663687f;  // 1/sqrt(32)

    // GEMM-side split: 2 (M, two m-tiles) x 4 (N)
    const int wrow = (lw & 1) << 5;          // 0 / 32
    const int wq0  = (lw >> 1) * 96;         // phase-1 col base
    // ATT-side: attention 2 warps/head; phase-3 split 2(M) x 4(N)
    const int ah = lw & 3, amh = lw >> 2;
    const int wc = (lw >> 1) << 5;           // phase-3 col base

    // ---- one-time init: zero buffers, resident weights ----
    {
        uint2* bz = reinterpret_cast<uint2*>(sh + BUF_OFF);
        for (int i = tid; i < 2 * BUF_SZ / 4; i += 512) bz[i] = make_uint2(0u, 0u);
        for (int i = tid; i < 128 * 384; i += 512) {
            int r = i / 384, c = i - r * 384;
            wq[r * WQ_P + c] = __float2half_rn(Wqkv[i]);
        }
        for (int i = tid; i < 128 * 128; i += 512) {
            int r = i >> 7, c = i & 127;
            wm[r * WM_P + c] = __float2half_rn(Wmerge[i]);
        }
    }
    __syncthreads();

    const int bid0 = blockIdx.x, grid = gridDim.x;
    const int lastk = (nwin - 1 - bid0) / grid;   // >=0 since grid < nwin

    // x loader (ATT group, 256 threads): fp32 global -> fp16 V rows 0..48
    auto load_x = [&](int w, __half* bufV) {
        const float* src = x + (size_t)w * (PW * DD);
        #pragma unroll
        for (int t = 0; t < 7; t++) {
            int idx = gtid + t * 256;
            if (idx < PW * 32) {
                int row = idx >> 5, c4 = (idx & 31) << 2;
                float4 f = __ldg(reinterpret_cast<const float4*>(src + row * DD + c4));
                uint2 st; st.x = f2h2(f.x, f.y); st.y = f2h2(f.z, f.w);
                *reinterpret_cast<uint2*>(bufV + row * BP + c4) = st;
            }
        }
    };

    if (!isGemm) load_x(bid0, sh + BUF_OFF + V_ROFF);   // x(0) -> buf0

    for (int k = 0; k <= lastk + 1; k++) {
        __syncthreads();   // publishes: x(k) [ATT,k-1], attn/phase3 frees, phase1(k-1)

        if (isGemm) {
            if (k > lastk) continue;
            const int b = k & 1;
            __half* bQ = sh + BUF_OFF + b * BUF_SZ;
            __half* bK = bQ + K_ROFF;
            __half* bV = bQ + V_ROFF;
            const uint32_t v_s = cvta_s(bV);

            // A fragments: x rows wrow..wrow+31 from V
            uint32_t af[2][8][4];
            #pragma unroll
            for (int mt = 0; mt < 2; mt++) {
                uint32_t a0 = v_s + (((wrow + mt * 16) + (lane & 15)) * BP
                                     + ((lane >> 4) << 3)) * 2;
                #pragma unroll
                for (int kk = 0; kk < 8; kk++)
                    LDSM4(af[mt][kk][0], af[mt][kk][1], af[mt][kk][2], af[mt][kk][3],
                          a0 + kk * 32);
            }
            gbar(1);       // all GEMM warps captured A before V overwrites

            // ---- phase 1: qkv = x @ Wqkv + bqkv ----
            #pragma unroll
            for (int p = 0; p < 6; p++) {
                const int c0 = wq0 + p * 16;
                float acc[2][2][4];
                #pragma unroll
                for (int nt = 0; nt < 2; nt++) {
                    int col = c0 + nt * 8 + ((lane & 3) << 1);
                    float b0 = __ldg(bqkv + col), b1 = __ldg(bqkv + col + 1);
                    #pragma unroll
                    for (int mt = 0; mt < 2; mt++) {
                        acc[mt][nt][0] = b0; acc[mt][nt][1] = b1;
                        acc[mt][nt][2] = b0; acc[mt][nt][3] = b1;
                    }
                }
                uint32_t wb0 = wq_s + ((lane & 15) * WQ_P + c0 + ((lane >> 4) << 3)) * 2;
                #pragma unroll
                for (int kk = 0; kk < 8; kk++) {
                    uint32_t b2[4];
                    LDSM4T(b2[0], b2[1], b2[2], b2[3], wb0 + (kk * 16 * WQ_P) * 2);
                    #pragma unroll
                    for (int mt = 0; mt < 2; mt++) {
                        MMA(acc[mt][0][0],acc[mt][0][1],acc[mt][0][2],acc[mt][0][3],
                            af[mt][kk][0],af[mt][kk][1],af[mt][kk][2],af[mt][kk][3],
                            b2[0], b2[1]);
                        MMA(acc[mt][1][0],acc[mt][1][1],acc[mt][1][2],acc[mt][1][3],
                            af[mt][kk][0],af[mt][kk][1],af[mt][kk][2],af[mt][kk][3],
                            b2[2], b2[3]);
                    }
                }
                const float mul = (c0 < 128) ? scale : 1.0f;
                __half* dstb = (c0 < 128) ? (bQ + c0)
                            : (c0 < 256) ? (bK + c0 - 128)
                                         : (bV + c0 - 256);
                #pragma unroll
                for (int mt = 0; mt < 2; mt++) {
                    const int r0 = wrow + mt * 16 + (lane >> 2);
                    #pragma unroll
                    for (int nt = 0; nt < 2; nt++) {
                        int cl = nt * 8 + ((lane & 3) << 1);
                        if (r0 < PW)
                            *reinterpret_cast<__half2*>(dstb + r0 * BP + cl) =
                                __floats2half2_rn(acc[mt][nt][0] * mul, acc[mt][nt][1] * mul);
                        if (r0 + 8 < PW)
                            *reinterpret_cast<__half2*>(dstb + (r0 + 8) * BP + cl) =
                                __floats2half2_rn(acc[mt][nt][2] * mul, acc[mt][nt][3] * mul);
                    }
                }
            }
        } else {
            // ================= ATT group =================
            if (k == 0) {
                if (lastk >= 1)
                    load_x(bid0 + grid, sh + BUF_OFF + BUF_SZ + V_ROFF);  // x(1)->buf1
                continue;
            }
            if (k - 1 > lastk) continue;
            const int b = (k - 1) & 1;
            const int win = bid0 + (k - 1) * grid;
            __half* bQ = sh + BUF_OFF + b * BUF_SZ;
            __half* bK = bQ + K_ROFF;
            __half* bV = bQ + V_ROFF;
            const uint32_t q_s = cvta_s(bQ);
            const uint32_t k_s = cvta_s(bK);
            const uint32_t v_s = cvta_s(bV);

            // ---- attention (2 warps per head) ----
            {
                const int h = ah;
                uint32_t kb[7][4];
                #pragma unroll
                for (int nt = 0; nt < 7; nt++) {
                    uint32_t addr = k_s + ((nt * 8 + (lane & 7)) * BP
                                           + h * 32 + ((lane >> 3) << 3)) * 2;
                    LDSM4(kb[nt][0], kb[nt][1], kb[nt][2], kb[nt][3], addr);
                }
                const __half* bh = g_bias + h * (49 * 56) + ((lane & 3) << 1);

                #pragma unroll
                for (int mi = 0; mi < 2; mi++) {
                    const int m = amh * 2 + mi;
                    uint32_t qa[4], qa2[4];
                    uint32_t qaddr = q_s + ((m * 16 + (lane & 15)) * BP
                                            + h * 32 + ((lane >> 4) << 3)) * 2;
                    LDSM4(qa[0], qa[1], qa[2], qa[3], qaddr);
                    LDSM4(qa2[0], qa2[1], qa2[2], qa2[3], qaddr + 32);

                    float s[7][4];
                    #pragma unroll
                    for (int nt = 0; nt < 7; nt++) {
                        s[nt][0] = s[nt][1] = s[nt][2] = s[nt][3] = 0.f;
                        MMA(s[nt][0],s[nt][1],s[nt][2],s[nt][3],
                            qa[0],qa[1],qa[2],qa[3], kb[nt][0], kb[nt][1]);
                        MMA(s[nt][0],s[nt][1],s[nt][2],s[nt][3],
                            qa2[0],qa2[1],qa2[2],qa2[3], kb[nt][2], kb[nt][3]);
                    }

                    int i0 = m * 16 + (lane >> 2), i1 = i0 + 8;
                    int i0c = (i0 < PW) ? i0 : 0, i1c = (i1 < PW) ? i1 : 0;
                    const __half* bp0 = bh + i0c * 56;
                    const __half* bp1 = bh + i1c * 56;
                    #pragma unroll
                    for (int nt = 0; nt < 7; nt++) {
                        float2 b0 = __half22float2(
                            __ldg(reinterpret_cast<const __half2*>(bp0 + nt * 8)));
                        float2 b1 = __half22float2(
                            __ldg(reinterpret_cast<const __half2*>(bp1 + nt * 8)));
                        s[nt][0] += b0.x; s[nt][1] += b0.y;
                        s[nt][2] += b1.x; s[nt][3] += b1.y;
                    }

                    float ml = -1e30f, mh2 = -1e30f;
                    #pragma unroll
                    for (int nt = 0; nt < 7; nt++) {
                        ml  = fmaxf(ml,  fmaxf(s[nt][0], s[nt][1]));
                        mh2 = fmaxf(mh2, fmaxf(s[nt][2], s[nt][3]));
                    }
                    ml  = fmaxf(ml,  __shfl_xor_sync(0xffffffffu, ml, 1));
                    ml  = fmaxf(ml,  __shfl_xor_sync(0xffffffffu, ml, 2));
                    mh2 = fmaxf(mh2, __shfl_xor_sync(0xffffffffu, mh2, 1));
                    mh2 = fmaxf(mh2, __shfl_xor_sync(0xffffffffu, mh2, 2));
                    float sl = 0.f, shs = 0.f;
                    #pragma unroll
                    for (int nt = 0; nt < 7; nt++) {
                        s[nt][0] = __expf(s[nt][0] - ml);  sl  += s[nt][0];
                        s[nt][1] = __expf(s[nt][1] - ml);  sl  += s[nt][1];
                        s[nt][2] = __expf(s[nt][2] - mh2); shs += s[nt][2];
                        s[nt][3] = __expf(s[nt][3] - mh2); shs += s[nt][3];
                    }
                    sl  += __shfl_xor_sync(0xffffffffu, sl, 1);
                    sl  += __shfl_xor_sync(0xffffffffu, sl, 2);
                    shs += __shfl_xor_sync(0xffffffffu, shs, 1);
                    shs += __shfl_xor_sync(0xffffffffu, shs, 2);
                    const float il = 1.f / sl, ih = 1.f / shs;

                    uint32_t pa[4][4];
                    #pragma unroll
                    for (int kt = 0; kt < 4; kt++) {
                        int n0 = 2 * kt, n1 = 2 * kt + 1;
                        pa[kt][0] = f2h2(s[n0][0] * il, s[n0][1] * il);
                        pa[kt][1] = f2h2(s[n0][2] * ih, s[n0][3] * ih);
                        if (n1 < 7) {
                            pa[kt][2] = f2h2(s[n1][0] * il, s[n1][1] * il);
                            pa[kt][3] = f2h2(s[n1][2] * ih, s[n1][3] * ih);
                        } else { pa[kt][2] = 0u; pa[kt][3] = 0u; }
                    }

                    float o[4][4];
                    #pragma unroll
                    for (int d = 0; d < 4; d++) o[d][0]=o[d][1]=o[d][2]=o[d][3]=0.f;
                    #pragma unroll
                    for (int kt = 0; kt < 4; kt++) {
                        uint32_t vb[8];
                        #pragma unroll
                        for (int dp = 0; dp < 2; dp++) {
                            uint32_t addr = v_s + ((kt * 16 + (lane & 15)) * BP
                                                   + h * 32 + dp * 16 + ((lane >> 4) << 3)) * 2;
                            LDSM4T(vb[dp*4+0], vb[dp*4+1], vb[dp*4+2], vb[dp*4+3], addr);
                        }
                        MMA(o[0][0],o[0][1],o[0][2],o[0][3],
                            pa[kt][0],pa[kt][1],pa[kt][2],pa[kt][3], vb[0], vb[1]);
                        MMA(o[1][0],o[1][1],o[1][2],o[1][3],
                            pa[kt][0],pa[kt][1],pa[kt][2],pa[kt][3], vb[2], vb[3]);
                        MMA(o[2][0],o[2][1],o[2][2],o[2][3],
                            pa[kt][0],pa[kt][1],pa[kt][2],pa[kt][3], vb[4], vb[5]);
                        MMA(o[3][0],o[3][1],o[3][2],o[3][3],
                            pa[kt][0],pa[kt][1],pa[kt][2],pa[kt][3], vb[6], vb[7]);
                    }
                    const int orow = m * 16 + (lane >> 2);
                    #pragma unroll
                    for (int d = 0; d < 4; d++) {
                        int col = h * 32 + d * 8 + ((lane & 3) << 1);
                        if (orow < PW)
                            *reinterpret_cast<__half2*>(bQ + orow * BP + col) =
                                __floats2half2_rn(o[d][0], o[d][1]);
                        if (orow + 8 < PW)
                            *reinterpret_cast<__half2*>(bQ + (orow + 8) * BP + col) =
                                __floats2half2_rn(o[d][2], o[d][3]);
                    }
                }
            }
            gbar(2);       // attn-out complete; V reads done

            // ---- phase 3: out = attn_out @ Wmerge + bmerge ----
            {
                uint32_t af2[2][8][4];
                #pragma unroll
                for (int mt = 0; mt < 2; mt++) {
                    uint32_t a0 = q_s + (((wrow + mt * 16) + (lane & 15)) * BP
                                         + ((lane >> 4) << 3)) * 2;
                    #pragma unroll
                    for (int kk = 0; kk < 8; kk++)
                        LDSM4(af2[mt][kk][0], af2[mt][kk][1], af2[mt][kk][2], af2[mt][kk][3],
                              a0 + kk * 32);
                }
                float* obase = out + (size_t)win * (PW * DD);

                #pragma unroll
                for (int nh = 0; nh < 2; nh++) {
                    const int c0 = wc + nh * 16;
                    float acc[2][2][4];
                    #pragma unroll
                    for (int nt = 0; nt < 2; nt++) {
                        int col = c0 + nt * 8 + ((lane & 3) << 1);
                        float b0 = __ldg(bmerge + col), b1 = __ldg(bmerge + col + 1);
                        #pragma unroll
                        for (int mt = 0; mt < 2; mt++) {
                            acc[mt][nt][0] = b0; acc[mt][nt][1] = b1;
                            acc[mt][nt][2] = b0; acc[mt][nt][3] = b1;
                        }
                    }
                    uint32_t wm0 = wm_s + ((lane & 15) * WM_P + c0 + ((lane >> 4) << 3)) * 2;
                    #pragma unroll
                    for (int kk = 0; kk < 8; kk++) {
                        uint32_t b2[4];
                        LDSM4T(b2[0], b2[1], b2[2], b2[3], wm0 + (kk * 16 * WM_P) * 2);
                        #pragma unroll
                        for (int mt = 0; mt < 2; mt++) {
                            MMA(acc[mt][0][0],acc[mt][0][1],acc[mt][0][2],acc[mt][0][3],
                                af2[mt][kk][0],af2[mt][kk][1],af2[mt][kk][2],af2[mt][kk][3],
                                b2[0], b2[1]);
                            MMA(acc[mt][1][0],acc[mt][1][1],acc[mt][1][2],acc[mt][1][3],
                                af2[mt][kk][0],af2[mt][kk][1],af2[mt][kk][2],af2[mt][kk][3],
                                b2[2], b2[3]);
                        }
                    }
                    #pragma unroll
                    for (int mt = 0; mt < 2; mt++) {
                        const int r0 = wrow + mt * 16 + (lane >> 2);
                        #pragma unroll
                        for (int nt = 0; nt < 2; nt++) {
                            int col = c0 + nt * 8 + ((lane & 3) << 1);
                            if (r0 < PW)
                                *reinterpret_cast<float2*>(obase + r0 * DD + col) =
                                    make_float2(acc[mt][nt][0], acc[mt][nt][1]);
                            if (r0 + 8 < PW)
                                *reinterpret_cast<float2*>(obase + (r0 + 8) * DD + col) =
                                    make_float2(acc[mt][nt][2], acc[mt][nt][3]);
                        }
                    }
                }
            }

            // prefetch x(k+1) into buf (k+1)&1 (V reads of that parity done)
            if (k + 1 <= lastk)
                load_x(bid0 + (k + 1) * grid,
                       sh + BUF_OFF + ((k + 1) & 1) * BUF_SZ + V_ROFF);
        }
    }
}

extern "C" void kernel_launch(void* const* d_in, const int* in_sizes, int n_in,
                              void* d_out, int out_size)
{
    const float* x      = (const float*)d_in[0];
    const float* Wqkv   = (const float*)d_in[1];
    const float* bqkv   = (const float*)d_in[2];
    const float* Wmerge = (const float*)d_in[3];
    const float* bmerge = (const float*)d_in[4];
    const float* table  = (const float*)d_in[5];
    float* out = (float*)d_out;

    const int nwin = in_sizes[0] / (PW * DD);   // 16384

    prep_bias_kernel<<<43, 256>>>(table);

    int sms = 148;
    cudaDeviceGetAttribute(&sms, cudaDevAttrMultiProcessorCount, 0);

    cudaFuncSetAttribute(rpmha_ws_kernel,
                         cudaFuncAttributeMaxDynamicSharedMemorySize, SMEM_BYTES);
    rpmha_ws_kernel<<<sms, 512, SMEM_BYTES>>>(x, Wqkv, bqkv, Wmerge, bmerge,
                                              out, nwin);
}

// round 15
// speedup vs baseline: 1.1919x; 1.1919x over previous
#include <cuda_runtime.h>
#include <cuda_fp16.h>
#include <cstdint>
#include <math.h>

#define PW 49
#define DD 128

// masked rel-pos bias, fp16, [4 heads][49 i][56 j] (j>=49 -> -60000)
__device__ __half g_bias[4 * 49 * 56];

__global__ void prep_bias_kernel(const float* __restrict__ table)
{
    int t = blockIdx.x * 256 + threadIdx.x;
    if (t >= 4 * 49 * 56) return;
    int h = t / (49 * 56);
    int rem = t - h * (49 * 56);
    int i = rem / 56, j = rem - i * 56;
    float v = -60000.0f;
    if (j < PW) {
        int ri = i / 7, ci = i - ri * 7;
        int rj = j / 7, cj = j - rj * 7;
        v = table[(((ri - rj + 6) * 13) + (ci - cj + 6)) * 4 + h];
    }
    g_bias[t] = __float2half_rn(v);
}

// ---------------- smem layout (halfs) ----------------
// wq  [128][392] : resident Wqkv fp16 (shared by both groups)
// wm  [128][136] : resident Wmerge fp16
// buf[g] (g=0,1): Q rows 0..55 | K rows 56..111 | V rows 112..175, pitch 136.
//   V doubles as x staging; Q doubles as attn-out. Pad rows zeroed once,
//   stores guarded row<49 so they stay zero.
static constexpr int WQ_P = 392;
static constexpr int WM_P = 136;
static constexpr int BP   = 136;
static constexpr int WQ_OFF  = 0;
static constexpr int WM_OFF  = 128 * WQ_P;             // 50176
static constexpr int BUF_OFF = WM_OFF + 128 * WM_P;    // 67584
static constexpr int K_ROFF  = 56 * BP;
static constexpr int V_ROFF  = 112 * BP;
static constexpr int BUF_SZ  = 176 * BP;               // 23936
static constexpr int HALFS   = BUF_OFF + 2 * BUF_SZ;   // 115456
static constexpr int SMEM_BYTES = HALFS * 2;           // 230912

__device__ __forceinline__ uint32_t cvta_s(const void* p)
{
    return (uint32_t)__cvta_generic_to_shared(p);
}
__device__ __forceinline__ uint32_t f2h2(float a, float b)
{
    __half2 h = __floats2half2_rn(a, b);
    return *reinterpret_cast<uint32_t*>(&h);
}
__device__ __forceinline__ void gbar(int id)
{
    asm volatile("bar.sync %0, %1;" :: "r"(id), "r"(256) : "memory");
}

#define LDSM4(R0,R1,R2,R3,ADDR) \
    asm volatile("ldmatrix.sync.aligned.m8n8.x4.shared.b16 {%0,%1,%2,%3},[%4];" \
        : "=r"(R0),"=r"(R1),"=r"(R2),"=r"(R3) : "r"(ADDR))
#define LDSM4T(R0,R1,R2,R3,ADDR) \
    asm volatile("ldmatrix.sync.aligned.m8n8.x4.trans.shared.b16 {%0,%1,%2,%3},[%4];" \
        : "=r"(R0),"=r"(R1),"=r"(R2),"=r"(R3) : "r"(ADDR))
#define MMA(C0,C1,C2,C3,A0,A1,A2,A3,B0,B1) \
    asm volatile("mma.sync.aligned.m16n8k16.row.col.f32.f16.f16.f32 " \
        "{%0,%1,%2,%3},{%4,%5,%6,%7},{%8,%9},{%0,%1,%2,%3};" \
        : "+f"(C0),"+f"(C1),"+f"(C2),"+f"(C3) \
        : "r"(A0),"r"(A1),"r"(A2),"r"(A3),"r"(B0),"r"(B1))

__global__ void __launch_bounds__(512, 1)
rpmha_dual5_kernel(const float* __restrict__ x,
                   const float* __restrict__ Wqkv,
                   const float* __restrict__ bqkv,
                   const float* __restrict__ Wmerge,
                   const float* __restrict__ bmerge,
                   float* __restrict__ out, int nwin)
{
    extern __shared__ __half sh[];
    __half* wq = sh + WQ_OFF;
    __half* wm = sh + WM_OFF;

    const int tid = threadIdx.x, warp = tid >> 5, lane = tid & 31;
    const int g    = warp >> 3;        // window group 0/1
    const int lw   = warp & 7;         // warp within group
    const int gtid = tid & 255;
    const int bid  = g + 1;            // named barrier id

    __half* bufQ = sh + BUF_OFF + g * BUF_SZ;
    __half* bufK = bufQ + K_ROFF;
    __half* bufV = bufQ + V_ROFF;
    const uint32_t q_s  = cvta_s(bufQ);
    const uint32_t k_s  = cvta_s(bufK);
    const uint32_t v_s  = cvta_s(bufV);
    const uint32_t wq_s = cvta_s(wq);
    const uint32_t wm_s = cvta_s(wm);
    const float scale = 0.17677669529663687f;  // 1/sqrt(32)

    // GEMM split: 2 (M, two m-tiles each) x 4 (N) -> B fragments reused
    const int wrow = (lw & 1) << 5;          // 0 / 32
    const int wq0  = (lw >> 1) * 96;         // phase-1 col base
    const int wc   = (lw >> 1) << 5;         // phase-3 col base
    // attention: 2 warps per head
    const int ah = lw & 3, amh = lw >> 2;

    // ---- one-time init: zero both buffers, load resident weights ----
    {
        uint2* bz = reinterpret_cast<uint2*>(sh + BUF_OFF);
        for (int i = tid; i < 2 * BUF_SZ / 4; i += 512) bz[i] = make_uint2(0u, 0u);
        for (int i = tid; i < 128 * 384; i += 512) {
            int r = i / 384, c = i - r * 384;
            wq[r * WQ_P + c] = __float2half_rn(Wqkv[i]);
        }
        for (int i = tid; i < 128 * 128; i += 512) {
            int r = i >> 7, c = i & 127;
            wm[r * WM_P + c] = __float2half_rn(Wmerge[i]);
        }
    }
    __syncthreads();

    const int stride = 2 * gridDim.x;
    int win = blockIdx.x * 2 + g;

    // x loader: fp32 global -> fp16 V rows 0..48 (pads stay zero)
    auto load_x = [&](int w) {
        const float* src = x + (size_t)w * (PW * DD);
        #pragma unroll
        for (int t = 0; t < 7; t++) {
            int idx = gtid + t * 256;
            if (idx < PW * 32) {
                int row = idx >> 5, c4 = (idx & 31) << 2;
                float4 f = __ldg(reinterpret_cast<const float4*>(src + row * DD + c4));
                uint2 st; st.x = f2h2(f.x, f.y); st.y = f2h2(f.z, f.w);
                *reinterpret_cast<uint2*>(bufV + row * BP + c4) = st;
            }
        }
    };

    if (win < nwin) load_x(win);

    for (; win < nwin; win += stride) {
        gbar(bid);                         // (1) x in V; prev attn+phase3 done

        // ---- A fragments: x rows wrow..wrow+31 (2 m-tiles) from V ----
        uint32_t af[2][8][4];
        #pragma unroll
        for (int mt = 0; mt < 2; mt++) {
            uint32_t a0 = v_s + (((wrow + mt * 16) + (lane & 15)) * BP
                                 + ((lane >> 4) << 3)) * 2;
            #pragma unroll
            for (int kk = 0; kk < 8; kk++)
                LDSM4(af[mt][kk][0], af[mt][kk][1], af[mt][kk][2], af[mt][kk][3],
                      a0 + kk * 32);
        }
        gbar(bid);                         // (2) A captured before V overwritten
                                           //     (cross-warp column hazard!)

        // ================= Phase 1: qkv = x @ Wqkv + bqkv =================
        #pragma unroll
        for (int p = 0; p < 6; p++) {
            const int c0 = wq0 + p * 16;
            float acc[2][2][4];
            #pragma unroll
            for (int nt = 0; nt < 2; nt++) {
                int col = c0 + nt * 8 + ((lane & 3) << 1);
                float b0 = __ldg(bqkv + col), b1 = __ldg(bqkv + col + 1);
                #pragma unroll
                for (int mt = 0; mt < 2; mt++) {
                    acc[mt][nt][0] = b0; acc[mt][nt][1] = b1;
                    acc[mt][nt][2] = b0; acc[mt][nt][3] = b1;
                }
            }
            uint32_t wb0 = wq_s + ((lane & 15) * WQ_P + c0 + ((lane >> 4) << 3)) * 2;
            // software-pipelined B fragments: LDSM for kk+1 issues before
            // the MMAs of kk, hiding LDS latency under tensor work
            uint32_t bcur[4], bnxt[4];
            LDSM4T(bcur[0], bcur[1], bcur[2], bcur[3], wb0);
            #pragma unroll
            for (int kk = 0; kk < 8; kk++) {
                if (kk < 7)
                    LDSM4T(bnxt[0], bnxt[1], bnxt[2], bnxt[3],
                           wb0 + ((kk + 1) * 16 * WQ_P) * 2);
                #pragma unroll
                for (int mt = 0; mt < 2; mt++) {
                    MMA(acc[mt][0][0],acc[mt][0][1],acc[mt][0][2],acc[mt][0][3],
                        af[mt][kk][0],af[mt][kk][1],af[mt][kk][2],af[mt][kk][3],
                        bcur[0], bcur[1]);
                    MMA(acc[mt][1][0],acc[mt][1][1],acc[mt][1][2],acc[mt][1][3],
                        af[mt][kk][0],af[mt][kk][1],af[mt][kk][2],af[mt][kk][3],
                        bcur[2], bcur[3]);
                }
                bcur[0] = bnxt[0]; bcur[1] = bnxt[1];
                bcur[2] = bnxt[2]; bcur[3] = bnxt[3];
            }
            const float mul = (c0 < 128) ? scale : 1.0f;
            __half* dstb = (c0 < 128) ? (bufQ + c0)
                        : (c0 < 256) ? (bufK + c0 - 128)
                                     : (bufV + c0 - 256);
            #pragma unroll
            for (int mt = 0; mt < 2; mt++) {
                const int r0 = wrow + mt * 16 + (lane >> 2);
                #pragma unroll
                for (int nt = 0; nt < 2; nt++) {
                    int cl = nt * 8 + ((lane & 3) << 1);
                    if (r0 < PW)
                        *reinterpret_cast<__half2*>(dstb + r0 * BP + cl) =
                            __floats2half2_rn(acc[mt][nt][0] * mul, acc[mt][nt][1] * mul);
                    if (r0 + 8 < PW)
                        *reinterpret_cast<__half2*>(dstb + (r0 + 8) * BP + cl) =
                            __floats2half2_rn(acc[mt][nt][2] * mul, acc[mt][nt][3] * mul);
                }
            }
        }
        gbar(bid);                         // (3) qkv ready

        // ============ Phase 2: attention (2 warps per head) ============
        {
            const int h = ah;
            uint32_t kb[7][4];
            #pragma unroll
            for (int nt = 0; nt < 7; nt++) {
                uint32_t addr = k_s + ((nt * 8 + (lane & 7)) * BP
                                       + h * 32 + ((lane >> 3) << 3)) * 2;
                LDSM4(kb[nt][0], kb[nt][1], kb[nt][2], kb[nt][3], addr);
            }
            const __half* bh = g_bias + h * (49 * 56) + ((lane & 3) << 1);

            #pragma unroll
            for (int mi = 0; mi < 2; mi++) {
                const int m = amh * 2 + mi;
                uint32_t qa[4], qa2[4];
                uint32_t qaddr = q_s + ((m * 16 + (lane & 15)) * BP
                                        + h * 32 + ((lane >> 4) << 3)) * 2;
                LDSM4(qa[0], qa[1], qa[2], qa[3], qaddr);
                LDSM4(qa2[0], qa2[1], qa2[2], qa2[3], qaddr + 32);

                float s[7][4];
                #pragma unroll
                for (int nt = 0; nt < 7; nt++) {
                    s[nt][0] = s[nt][1] = s[nt][2] = s[nt][3] = 0.f;
                    MMA(s[nt][0],s[nt][1],s[nt][2],s[nt][3],
                        qa[0],qa[1],qa[2],qa[3], kb[nt][0], kb[nt][1]);
                    MMA(s[nt][0],s[nt][1],s[nt][2],s[nt][3],
                        qa2[0],qa2[1],qa2[2],qa2[3], kb[nt][2], kb[nt][3]);
                }

                int i0 = m * 16 + (lane >> 2), i1 = i0 + 8;
                int i0c = (i0 < PW) ? i0 : 0, i1c = (i1 < PW) ? i1 : 0;
                const __half* bp0 = bh + i0c * 56;
                const __half* bp1 = bh + i1c * 56;
                #pragma unroll
                for (int nt = 0; nt < 7; nt++) {
                    float2 b0 = __half22float2(
                        __ldg(reinterpret_cast<const __half2*>(bp0 + nt * 8)));
                    float2 b1 = __half22float2(
                        __ldg(reinterpret_cast<const __half2*>(bp1 + nt * 8)));
                    s[nt][0] += b0.x; s[nt][1] += b0.y;
                    s[nt][2] += b1.x; s[nt][3] += b1.y;
                }

                float ml = -1e30f, mh2 = -1e30f;
                #pragma unroll
                for (int nt = 0; nt < 7; nt++) {
                    ml  = fmaxf(ml,  fmaxf(s[nt][0], s[nt][1]));
                    mh2 = fmaxf(mh2, fmaxf(s[nt][2], s[nt][3]));
                }
                ml  = fmaxf(ml,  __shfl_xor_sync(0xffffffffu, ml, 1));
                ml  = fmaxf(ml,  __shfl_xor_sync(0xffffffffu, ml, 2));
                mh2 = fmaxf(mh2, __shfl_xor_sync(0xffffffffu, mh2, 1));
                mh2 = fmaxf(mh2, __shfl_xor_sync(0xffffffffu, mh2, 2));
                float sl = 0.f, shs = 0.f;
                #pragma unroll
                for (int nt = 0; nt < 7; nt++) {
                    s[nt][0] = __expf(s[nt][0] - ml);  sl  += s[nt][0];
                    s[nt][1] = __expf(s[nt][1] - ml);  sl  += s[nt][1];
                    s[nt][2] = __expf(s[nt][2] - mh2); shs += s[nt][2];
                    s[nt][3] = __expf(s[nt][3] - mh2); shs += s[nt][3];
                }
                sl  += __shfl_xor_sync(0xffffffffu, sl, 1);
                sl  += __shfl_xor_sync(0xffffffffu, sl, 2);
                shs += __shfl_xor_sync(0xffffffffu, shs, 1);
                shs += __shfl_xor_sync(0xffffffffu, shs, 2);
                const float il = 1.f / sl, ih = 1.f / shs;

                uint32_t pa[4][4];
                #pragma unroll
                for (int kt = 0; kt < 4; kt++) {
                    int n0 = 2 * kt, n1 = 2 * kt + 1;
                    pa[kt][0] = f2h2(s[n0][0] * il, s[n0][1] * il);
                    pa[kt][1] = f2h2(s[n0][2] * ih, s[n0][3] * ih);
                    if (n1 < 7) {
                        pa[kt][2] = f2h2(s[n1][0] * il, s[n1][1] * il);
                        pa[kt][3] = f2h2(s[n1][2] * ih, s[n1][3] * ih);
                    } else { pa[kt][2] = 0u; pa[kt][3] = 0u; }
                }

                float o[4][4];
                #pragma unroll
                for (int d = 0; d < 4; d++) o[d][0]=o[d][1]=o[d][2]=o[d][3]=0.f;
                #pragma unroll
                for (int kt = 0; kt < 4; kt++) {
                    uint32_t vb[8];            // transient (reg-pressure cap)
                    #pragma unroll
                    for (int dp = 0; dp < 2; dp++) {
                        uint32_t addr = v_s + ((kt * 16 + (lane & 15)) * BP
                                               + h * 32 + dp * 16 + ((lane >> 4) << 3)) * 2;
                        LDSM4T(vb[dp*4+0], vb[dp*4+1], vb[dp*4+2], vb[dp*4+3], addr);
                    }
                    MMA(o[0][0],o[0][1],o[0][2],o[0][3],
                        pa[kt][0],pa[kt][1],pa[kt][2],pa[kt][3], vb[0], vb[1]);
                    MMA(o[1][0],o[1][1],o[1][2],o[1][3],
                        pa[kt][0],pa[kt][1],pa[kt][2],pa[kt][3], vb[2], vb[3]);
                    MMA(o[2][0],o[2][1],o[2][2],o[2][3],
                        pa[kt][0],pa[kt][1],pa[kt][2],pa[kt][3], vb[4], vb[5]);
                    MMA(o[3][0],o[3][1],o[3][2],o[3][3],
                        pa[kt][0],pa[kt][1],pa[kt][2],pa[kt][3], vb[6], vb[7]);
                }
                const int orow = m * 16 + (lane >> 2);
                #pragma unroll
                for (int d = 0; d < 4; d++) {
                    int col = h * 32 + d * 8 + ((lane & 3) << 1);
                    if (orow < PW)
                        *reinterpret_cast<__half2*>(bufQ + orow * BP + col) =
                            __floats2half2_rn(o[d][0], o[d][1]);
                    if (orow + 8 < PW)
                        *reinterpret_cast<__half2*>(bufQ + (orow + 8) * BP + col) =
                            __floats2half2_rn(o[d][2], o[d][3]);
                }
            }
        }
        gbar(bid);                         // (4) attn-out ready; V free

        if (win + stride < nwin) load_x(win + stride);   // overlaps phase 3

        // ============ Phase 3: out = attn_out @ Wmerge + bmerge ============
        {
            uint32_t af2[2][8][4];
            #pragma unroll
            for (int mt = 0; mt < 2; mt++) {
                uint32_t a0 = q_s + (((wrow + mt * 16) + (lane & 15)) * BP
                                     + ((lane >> 4) << 3)) * 2;
                #pragma unroll
                for (int kk = 0; kk < 8; kk++)
                    LDSM4(af2[mt][kk][0], af2[mt][kk][1], af2[mt][kk][2], af2[mt][kk][3],
                          a0 + kk * 32);
            }
            float* obase = out + (size_t)win * (PW * DD);

            #pragma unroll
            for (int nh = 0; nh < 2; nh++) {
                const int c0 = wc + nh * 16;
                float acc[2][2][4];
                #pragma unroll
                for (int nt = 0; nt < 2; nt++) {
                    int col = c0 + nt * 8 + ((lane & 3) << 1);
                    float b0 = __ldg(bmerge + col), b1 = __ldg(bmerge + col + 1);
                    #pragma unroll
                    for (int mt = 0; mt < 2; mt++) {
                        acc[mt][nt][0] = b0; acc[mt][nt][1] = b1;
                        acc[mt][nt][2] = b0; acc[mt][nt][3] = b1;
                    }
                }
                uint32_t wm0 = wm_s + ((lane & 15) * WM_P + c0 + ((lane >> 4) << 3)) * 2;
                uint32_t bcur[4], bnxt[4];
                LDSM4T(bcur[0], bcur[1], bcur[2], bcur[3], wm0);
                #pragma unroll
                for (int kk = 0; kk < 8; kk++) {
                    if (kk < 7)
                        LDSM4T(bnxt[0], bnxt[1], bnxt[2], bnxt[3],
                               wm0 + ((kk + 1) * 16 * WM_P) * 2);
                    #pragma unroll
                    for (int mt = 0; mt < 2; mt++) {
                        MMA(acc[mt][0][0],acc[mt][0][1],acc[mt][0][2],acc[mt][0][3],
                            af2[mt][kk][0],af2[mt][kk][1],af2[mt][kk][2],af2[mt][kk][3],
                            bcur[0], bcur[1]);
                        MMA(acc[mt][1][0],acc[mt][1][1],acc[mt][1][2],acc[mt][1][3],
                            af2[mt][kk][0],af2[mt][kk][1],af2[mt][kk][2],af2[mt][kk][3],
                            bcur[2], bcur[3]);
                    }
                    bcur[0] = bnxt[0]; bcur[1] = bnxt[1];
                    bcur[2] = bnxt[2]; bcur[3] = bnxt[3];
                }
                #pragma unroll
                for (int mt = 0; mt < 2; mt++) {
                    const int r0 = wrow + mt * 16 + (lane >> 2);
                    #pragma unroll
                    for (int nt = 0; nt < 2; nt++) {
                        int col = c0 + nt * 8 + ((lane & 3) << 1);
                        if (r0 < PW)
                            *reinterpret_cast<float2*>(obase + r0 * DD + col) =
                                make_float2(acc[mt][nt][0], acc[mt][nt][1]);
                        if (r0 + 8 < PW)
                            *reinterpret_cast<float2*>(obase + (r0 + 8) * DD + col) =
                                make_float2(acc[mt][nt][2], acc[mt][nt][3]);
                    }
                }
            }
        }
    }
}

extern "C" void kernel_launch(void* const* d_in, const int* in_sizes, int n_in,
                              void* d_out, int out_size)
{
    const float* x      = (const float*)d_in[0];
    const float* Wqkv   = (const float*)d_in[1];
    const float* bqkv   = (const float*)d_in[2];
    const float* Wmerge = (const float*)d_in[3];
    const float* bmerge = (const float*)d_in[4];
    const float* table  = (const float*)d_in[5];
    float* out = (float*)d_out;

    const int nwin = in_sizes[0] / (PW * DD);   // 16384

    prep_bias_kernel<<<43, 256>>>(table);

    int sms = 148;
    cudaDeviceGetAttribute(&sms, cudaDevAttrMultiProcessorCount, 0);

    cudaFuncSetAttribute(rpmha_dual5_kernel,
                         cudaFuncAttributeMaxDynamicSharedMemorySize, SMEM_BYTES);
    rpmha_dual5_kernel<<<sms, 512, SMEM_BYTES>>>(x, Wqkv, bqkv, Wmerge, bmerge,
                                                 out, nwin);
}

// round 16
// speedup vs baseline: 1.2117x; 1.0166x over previous
#include <cuda_runtime.h>
#include <cuda_fp16.h>
#include <cstdint>
#include <math.h>

#define PW 49
#define DD 128

// masked rel-pos bias, fp16, [4 heads][49 i][56 j] (j>=49 -> -60000)
__device__ __half g_bias[4 * 49 * 56];

__global__ void prep_bias_kernel(const float* __restrict__ table)
{
    int t = blockIdx.x * 256 + threadIdx.x;
    if (t >= 4 * 49 * 56) return;
    int h = t / (49 * 56);
    int rem = t - h * (49 * 56);
    int i = rem / 56, j = rem - i * 56;
    float v = -60000.0f;
    if (j < PW) {
        int ri = i / 7, ci = i - ri * 7;
        int rj = j / 7, cj = j - rj * 7;
        v = table[(((ri - rj + 6) * 13) + (ci - cj + 6)) * 4 + h];
    }
    g_bias[t] = __float2half_rn(v);
}

// ---------------- smem layout (halfs) ----------------
// wq  [128][392] : resident Wqkv fp16 (shared by both groups)
// wm  [128][136] : resident Wmerge fp16
// buf[g] (g=0,1): Q rows 0..55 | K rows 56..111 | V rows 112..175, pitch 136.
//   V doubles as x staging; Q doubles as attn-out. Pad rows zeroed once,
//   stores guarded row<49 so they stay zero.
static constexpr int WQ_P = 392;
static constexpr int WM_P = 136;
static constexpr int BP   = 136;
static constexpr int WQ_OFF  = 0;
static constexpr int WM_OFF  = 128 * WQ_P;             // 50176
static constexpr int BUF_OFF = WM_OFF + 128 * WM_P;    // 67584
static constexpr int K_ROFF  = 56 * BP;
static constexpr int V_ROFF  = 112 * BP;
static constexpr int BUF_SZ  = 176 * BP;               // 23936
static constexpr int HALFS   = BUF_OFF + 2 * BUF_SZ;   // 115456
static constexpr int SMEM_BYTES = HALFS * 2;           // 230912

__device__ __forceinline__ uint32_t cvta_s(const void* p)
{
    return (uint32_t)__cvta_generic_to_shared(p);
}
__device__ __forceinline__ uint32_t f2h2(float a, float b)
{
    __half2 h = __floats2half2_rn(a, b);
    return *reinterpret_cast<uint32_t*>(&h);
}
__device__ __forceinline__ void gbar(int id)
{
    asm volatile("bar.sync %0, %1;" :: "r"(id), "r"(256) : "memory");
}

#define LDSM4(R0,R1,R2,R3,ADDR) \
    asm volatile("ldmatrix.sync.aligned.m8n8.x4.shared.b16 {%0,%1,%2,%3},[%4];" \
        : "=r"(R0),"=r"(R1),"=r"(R2),"=r"(R3) : "r"(ADDR))
#define LDSM4T(R0,R1,R2,R3,ADDR) \
    asm volatile("ldmatrix.sync.aligned.m8n8.x4.trans.shared.b16 {%0,%1,%2,%3},[%4];" \
        : "=r"(R0),"=r"(R1),"=r"(R2),"=r"(R3) : "r"(ADDR))
#define MMA(C0,C1,C2,C3,A0,A1,A2,A3,B0,B1) \
    asm volatile("mma.sync.aligned.m16n8k16.row.col.f32.f16.f16.f32 " \
        "{%0,%1,%2,%3},{%4,%5,%6,%7},{%8,%9},{%0,%1,%2,%3};" \
        : "+f"(C0),"+f"(C1),"+f"(C2),"+f"(C3) \
        : "r"(A0),"r"(A1),"r"(A2),"r"(A3),"r"(B0),"r"(B1))

__global__ void __launch_bounds__(512, 1)
rpmha_dual6_kernel(const float* __restrict__ x,
                   const float* __restrict__ Wqkv,
                   const float* __restrict__ bqkv,
                   const float* __restrict__ Wmerge,
                   const float* __restrict__ bmerge,
                   float* __restrict__ out, int nwin)
{
    extern __shared__ __half sh[];
    __half* wq = sh + WQ_OFF;
    __half* wm = sh + WM_OFF;

    const int tid = threadIdx.x, warp = tid >> 5, lane = tid & 31;
    const int g    = warp >> 3;        // window group 0/1
    const int lw   = warp & 7;         // warp within group
    const int gtid = tid & 255;
    const int bid  = g + 1;            // named barrier id

    __half* bufQ = sh + BUF_OFF + g * BUF_SZ;
    __half* bufK = bufQ + K_ROFF;
    __half* bufV = bufQ + V_ROFF;
    const uint32_t q_s  = cvta_s(bufQ);
    const uint32_t k_s  = cvta_s(bufK);
    const uint32_t v_s  = cvta_s(bufV);
    const uint32_t wq_s = cvta_s(wq);
    const uint32_t wm_s = cvta_s(wm);
    const float scale = 0.17677669529663687f;  // 1/sqrt(32)

    // GEMM split: 2 (M, two m-tiles each) x 4 (N) -> B fragments reused
    const int wrow = (lw & 1) << 5;          // 0 / 32
    const int wq0  = (lw >> 1) * 96;         // phase-1 col base
    const int wc   = (lw >> 1) << 5;         // phase-3 col base
    // attention: 2 warps per head, each warp owns 2 m-tiles (fused)
    const int ah = lw & 3, amh = lw >> 2;

    // ---- one-time init: zero both buffers, load resident weights ----
    {
        uint2* bz = reinterpret_cast<uint2*>(sh + BUF_OFF);
        for (int i = tid; i < 2 * BUF_SZ / 4; i += 512) bz[i] = make_uint2(0u, 0u);
        for (int i = tid; i < 128 * 384; i += 512) {
            int r = i / 384, c = i - r * 384;
            wq[r * WQ_P + c] = __float2half_rn(Wqkv[i]);
        }
        for (int i = tid; i < 128 * 128; i += 512) {
            int r = i >> 7, c = i & 127;
            wm[r * WM_P + c] = __float2half_rn(Wmerge[i]);
        }
    }
    __syncthreads();

    const int stride = 2 * gridDim.x;
    int win = blockIdx.x * 2 + g;

    // x loader: fp32 global -> fp16 V rows 0..48 (pads stay zero)
    auto load_x = [&](int w) {
        const float* src = x + (size_t)w * (PW * DD);
        #pragma unroll
        for (int t = 0; t < 7; t++) {
            int idx = gtid + t * 256;
            if (idx < PW * 32) {
                int row = idx >> 5, c4 = (idx & 31) << 2;
                float4 f = __ldg(reinterpret_cast<const float4*>(src + row * DD + c4));
                uint2 st; st.x = f2h2(f.x, f.y); st.y = f2h2(f.z, f.w);
                *reinterpret_cast<uint2*>(bufV + row * BP + c4) = st;
            }
        }
    };

    if (win < nwin) load_x(win);

    for (; win < nwin; win += stride) {
        gbar(bid);                         // (1) x in V; prev attn+phase3 done

        // ---- A fragments: x rows wrow..wrow+31 (2 m-tiles) from V ----
        uint32_t af[2][8][4];
        #pragma unroll
        for (int mt = 0; mt < 2; mt++) {
            uint32_t a0 = v_s + (((wrow + mt * 16) + (lane & 15)) * BP
                                 + ((lane >> 4) << 3)) * 2;
            #pragma unroll
            for (int kk = 0; kk < 8; kk++)
                LDSM4(af[mt][kk][0], af[mt][kk][1], af[mt][kk][2], af[mt][kk][3],
                      a0 + kk * 32);
        }
        gbar(bid);                         // (2) A captured before V overwritten

        // ================= Phase 1: qkv = x @ Wqkv + bqkv =================
        #pragma unroll
        for (int p = 0; p < 6; p++) {
            const int c0 = wq0 + p * 16;
            float acc[2][2][4];
            #pragma unroll
            for (int nt = 0; nt < 2; nt++) {
                int col = c0 + nt * 8 + ((lane & 3) << 1);
                float b0 = __ldg(bqkv + col), b1 = __ldg(bqkv + col + 1);
                #pragma unroll
                for (int mt = 0; mt < 2; mt++) {
                    acc[mt][nt][0] = b0; acc[mt][nt][1] = b1;
                    acc[mt][nt][2] = b0; acc[mt][nt][3] = b1;
                }
            }
            uint32_t wb0 = wq_s + ((lane & 15) * WQ_P + c0 + ((lane >> 4) << 3)) * 2;
            #pragma unroll
            for (int kk = 0; kk < 8; kk++) {
                uint32_t b[4];
                LDSM4T(b[0], b[1], b[2], b[3], wb0 + (kk * 16 * WQ_P) * 2);
                #pragma unroll
                for (int mt = 0; mt < 2; mt++) {
                    MMA(acc[mt][0][0],acc[mt][0][1],acc[mt][0][2],acc[mt][0][3],
                        af[mt][kk][0],af[mt][kk][1],af[mt][kk][2],af[mt][kk][3],
                        b[0], b[1]);
                    MMA(acc[mt][1][0],acc[mt][1][1],acc[mt][1][2],acc[mt][1][3],
                        af[mt][kk][0],af[mt][kk][1],af[mt][kk][2],af[mt][kk][3],
                        b[2], b[3]);
                }
            }
            const float mul = (c0 < 128) ? scale : 1.0f;
            __half* dstb = (c0 < 128) ? (bufQ + c0)
                        : (c0 < 256) ? (bufK + c0 - 128)
                                     : (bufV + c0 - 256);
            #pragma unroll
            for (int mt = 0; mt < 2; mt++) {
                const int r0 = wrow + mt * 16 + (lane >> 2);
                #pragma unroll
                for (int nt = 0; nt < 2; nt++) {
                    int cl = nt * 8 + ((lane & 3) << 1);
                    if (r0 < PW)
                        *reinterpret_cast<__half2*>(dstb + r0 * BP + cl) =
                            __floats2half2_rn(acc[mt][nt][0] * mul, acc[mt][nt][1] * mul);
                    if (r0 + 8 < PW)
                        *reinterpret_cast<__half2*>(dstb + (r0 + 8) * BP + cl) =
                            __floats2half2_rn(acc[mt][nt][2] * mul, acc[mt][nt][3] * mul);
                }
            }
        }
        gbar(bid);                         // (3) qkv ready

        // ====== Phase 2: attention — BOTH m-tiles fused for ILP ======
        {
            const int h = ah;
            const int m0 = amh * 2, m1 = m0 + 1;

            uint32_t kb[7][4];
            #pragma unroll
            for (int nt = 0; nt < 7; nt++) {
                uint32_t addr = k_s + ((nt * 8 + (lane & 7)) * BP
                                       + h * 32 + ((lane >> 3) << 3)) * 2;
                LDSM4(kb[nt][0], kb[nt][1], kb[nt][2], kb[nt][3], addr);
            }
            uint32_t qaA[8], qaB[8];
            {
                uint32_t qaddr = q_s + ((m0 * 16 + (lane & 15)) * BP
                                        + h * 32 + ((lane >> 4) << 3)) * 2;
                LDSM4(qaA[0], qaA[1], qaA[2], qaA[3], qaddr);
                LDSM4(qaA[4], qaA[5], qaA[6], qaA[7], qaddr + 32);
                qaddr = q_s + ((m1 * 16 + (lane & 15)) * BP
                               + h * 32 + ((lane >> 4) << 3)) * 2;
                LDSM4(qaB[0], qaB[1], qaB[2], qaB[3], qaddr);
                LDSM4(qaB[4], qaB[5], qaB[6], qaB[7], qaddr + 32);
            }

            // QK for both m-tiles (independent streams)
            float sA[7][4], sB[7][4];
            #pragma unroll
            for (int nt = 0; nt < 7; nt++) {
                sA[nt][0] = sA[nt][1] = sA[nt][2] = sA[nt][3] = 0.f;
                sB[nt][0] = sB[nt][1] = sB[nt][2] = sB[nt][3] = 0.f;
                MMA(sA[nt][0],sA[nt][1],sA[nt][2],sA[nt][3],
                    qaA[0],qaA[1],qaA[2],qaA[3], kb[nt][0], kb[nt][1]);
                MMA(sB[nt][0],sB[nt][1],sB[nt][2],sB[nt][3],
                    qaB[0],qaB[1],qaB[2],qaB[3], kb[nt][0], kb[nt][1]);
                MMA(sA[nt][0],sA[nt][1],sA[nt][2],sA[nt][3],
                    qaA[4],qaA[5],qaA[6],qaA[7], kb[nt][2], kb[nt][3]);
                MMA(sB[nt][0],sB[nt][1],sB[nt][2],sB[nt][3],
                    qaB[4],qaB[5],qaB[6],qaB[7], kb[nt][2], kb[nt][3]);
            }

            // bias for both
            const __half* bh = g_bias + h * (49 * 56) + ((lane & 3) << 1);
            int i0A = m0 * 16 + (lane >> 2), i1A = i0A + 8;
            int i0B = m1 * 16 + (lane >> 2), i1B = i0B + 8;
            const __half* bpA0 = bh + ((i0A < PW) ? i0A : 0) * 56;
            const __half* bpA1 = bh + ((i1A < PW) ? i1A : 0) * 56;
            const __half* bpB0 = bh + ((i0B < PW) ? i0B : 0) * 56;
            const __half* bpB1 = bh + ((i1B < PW) ? i1B : 0) * 56;
            #pragma unroll
            for (int nt = 0; nt < 7; nt++) {
                float2 a0 = __half22float2(__ldg(reinterpret_cast<const __half2*>(bpA0 + nt * 8)));
                float2 a1 = __half22float2(__ldg(reinterpret_cast<const __half2*>(bpA1 + nt * 8)));
                float2 b0 = __half22float2(__ldg(reinterpret_cast<const __half2*>(bpB0 + nt * 8)));
                float2 b1 = __half22float2(__ldg(reinterpret_cast<const __half2*>(bpB1 + nt * 8)));
                sA[nt][0] += a0.x; sA[nt][1] += a0.y;
                sA[nt][2] += a1.x; sA[nt][3] += a1.y;
                sB[nt][0] += b0.x; sB[nt][1] += b0.y;
                sB[nt][2] += b1.x; sB[nt][3] += b1.y;
            }

            // softmax for both (chains interleave)
            float mlA = -1e30f, mhA = -1e30f, mlB = -1e30f, mhB = -1e30f;
            #pragma unroll
            for (int nt = 0; nt < 7; nt++) {
                mlA = fmaxf(mlA, fmaxf(sA[nt][0], sA[nt][1]));
                mhA = fmaxf(mhA, fmaxf(sA[nt][2], sA[nt][3]));
                mlB = fmaxf(mlB, fmaxf(sB[nt][0], sB[nt][1]));
                mhB = fmaxf(mhB, fmaxf(sB[nt][2], sB[nt][3]));
            }
            mlA = fmaxf(mlA, __shfl_xor_sync(0xffffffffu, mlA, 1));
            mhA = fmaxf(mhA, __shfl_xor_sync(0xffffffffu, mhA, 1));
            mlB = fmaxf(mlB, __shfl_xor_sync(0xffffffffu, mlB, 1));
            mhB = fmaxf(mhB, __shfl_xor_sync(0xffffffffu, mhB, 1));
            mlA = fmaxf(mlA, __shfl_xor_sync(0xffffffffu, mlA, 2));
            mhA = fmaxf(mhA, __shfl_xor_sync(0xffffffffu, mhA, 2));
            mlB = fmaxf(mlB, __shfl_xor_sync(0xffffffffu, mlB, 2));
            mhB = fmaxf(mhB, __shfl_xor_sync(0xffffffffu, mhB, 2));
            float slA = 0.f, shA = 0.f, slB = 0.f, shB = 0.f;
            #pragma unroll
            for (int nt = 0; nt < 7; nt++) {
                sA[nt][0] = __expf(sA[nt][0] - mlA); slA += sA[nt][0];
                sA[nt][1] = __expf(sA[nt][1] - mlA); slA += sA[nt][1];
                sA[nt][2] = __expf(sA[nt][2] - mhA); shA += sA[nt][2];
                sA[nt][3] = __expf(sA[nt][3] - mhA); shA += sA[nt][3];
                sB[nt][0] = __expf(sB[nt][0] - mlB); slB += sB[nt][0];
                sB[nt][1] = __expf(sB[nt][1] - mlB); slB += sB[nt][1];
                sB[nt][2] = __expf(sB[nt][2] - mhB); shB += sB[nt][2];
                sB[nt][3] = __expf(sB[nt][3] - mhB); shB += sB[nt][3];
            }
            slA += __shfl_xor_sync(0xffffffffu, slA, 1);
            shA += __shfl_xor_sync(0xffffffffu, shA, 1);
            slB += __shfl_xor_sync(0xffffffffu, slB, 1);
            shB += __shfl_xor_sync(0xffffffffu, shB, 1);
            slA += __shfl_xor_sync(0xffffffffu, slA, 2);
            shA += __shfl_xor_sync(0xffffffffu, shA, 2);
            slB += __shfl_xor_sync(0xffffffffu, slB, 2);
            shB += __shfl_xor_sync(0xffffffffu, shB, 2);
            const float ilA = 1.f / slA, ihA = 1.f / shA;
            const float ilB = 1.f / slB, ihB = 1.f / shB;

            // P -> A fragments for both
            uint32_t paA[4][4], paB[4][4];
            #pragma unroll
            for (int kt = 0; kt < 4; kt++) {
                int n0 = 2 * kt, n1 = 2 * kt + 1;
                paA[kt][0] = f2h2(sA[n0][0] * ilA, sA[n0][1] * ilA);
                paA[kt][1] = f2h2(sA[n0][2] * ihA, sA[n0][3] * ihA);
                paB[kt][0] = f2h2(sB[n0][0] * ilB, sB[n0][1] * ilB);
                paB[kt][1] = f2h2(sB[n0][2] * ihB, sB[n0][3] * ihB);
                if (n1 < 7) {
                    paA[kt][2] = f2h2(sA[n1][0] * ilA, sA[n1][1] * ilA);
                    paA[kt][3] = f2h2(sA[n1][2] * ihA, sA[n1][3] * ihA);
                    paB[kt][2] = f2h2(sB[n1][0] * ilB, sB[n1][1] * ilB);
                    paB[kt][3] = f2h2(sB[n1][2] * ihB, sB[n1][3] * ihB);
                } else {
                    paA[kt][2] = 0u; paA[kt][3] = 0u;
                    paB[kt][2] = 0u; paB[kt][3] = 0u;
                }
            }

            // PV for both — vb loaded ONCE per kt (was loaded twice before)
            float oA[4][4], oB[4][4];
            #pragma unroll
            for (int d = 0; d < 4; d++) {
                oA[d][0]=oA[d][1]=oA[d][2]=oA[d][3]=0.f;
                oB[d][0]=oB[d][1]=oB[d][2]=oB[d][3]=0.f;
            }
            #pragma unroll
            for (int kt = 0; kt < 4; kt++) {
                uint32_t vb[8];
                #pragma unroll
                for (int dp = 0; dp < 2; dp++) {
                    uint32_t addr = v_s + ((kt * 16 + (lane & 15)) * BP
                                           + h * 32 + dp * 16 + ((lane >> 4) << 3)) * 2;
                    LDSM4T(vb[dp*4+0], vb[dp*4+1], vb[dp*4+2], vb[dp*4+3], addr);
                }
                #pragma unroll
                for (int d = 0; d < 4; d++) {
                    MMA(oA[d][0],oA[d][1],oA[d][2],oA[d][3],
                        paA[kt][0],paA[kt][1],paA[kt][2],paA[kt][3],
                        vb[2*d], vb[2*d+1]);
                    MMA(oB[d][0],oB[d][1],oB[d][2],oB[d][3],
                        paB[kt][0],paB[kt][1],paB[kt][2],paB[kt][3],
                        vb[2*d], vb[2*d+1]);
                }
            }

            // stores for both m-tiles
            const int orA = m0 * 16 + (lane >> 2);
            const int orB = m1 * 16 + (lane >> 2);
            #pragma unroll
            for (int d = 0; d < 4; d++) {
                int col = h * 32 + d * 8 + ((lane & 3) << 1);
                if (orA < PW)
                    *reinterpret_cast<__half2*>(bufQ + orA * BP + col) =
                        __floats2half2_rn(oA[d][0], oA[d][1]);
                if (orA + 8 < PW)
                    *reinterpret_cast<__half2*>(bufQ + (orA + 8) * BP + col) =
                        __floats2half2_rn(oA[d][2], oA[d][3]);
                if (orB < PW)
                    *reinterpret_cast<__half2*>(bufQ + orB * BP + col) =
                        __floats2half2_rn(oB[d][0], oB[d][1]);
                if (orB + 8 < PW)
                    *reinterpret_cast<__half2*>(bufQ + (orB + 8) * BP + col) =
                        __floats2half2_rn(oB[d][2], oB[d][3]);
            }
        }
        gbar(bid);                         // (4) attn-out ready; V free

        if (win + stride < nwin) load_x(win + stride);   // overlaps phase 3

        // ============ Phase 3: out = attn_out @ Wmerge + bmerge ============
        {
            uint32_t af2[2][8][4];
            #pragma unroll
            for (int mt = 0; mt < 2; mt++) {
                uint32_t a0 = q_s + (((wrow + mt * 16) + (lane & 15)) * BP
                                     + ((lane >> 4) << 3)) * 2;
                #pragma unroll
                for (int kk = 0; kk < 8; kk++)
                    LDSM4(af2[mt][kk][0], af2[mt][kk][1], af2[mt][kk][2], af2[mt][kk][3],
                          a0 + kk * 32);
            }
            float* obase = out + (size_t)win * (PW * DD);

            #pragma unroll
            for (int nh = 0; nh < 2; nh++) {
                const int c0 = wc + nh * 16;
                float acc[2][2][4];
                #pragma unroll
                for (int nt = 0; nt < 2; nt++) {
                    int col = c0 + nt * 8 + ((lane & 3) << 1);
                    float b0 = __ldg(bmerge + col), b1 = __ldg(bmerge + col + 1);
                    #pragma unroll
                    for (int mt = 0; mt < 2; mt++) {
                        acc[mt][nt][0] = b0; acc[mt][nt][1] = b1;
                        acc[mt][nt][2] = b0; acc[mt][nt][3] = b1;
                    }
                }
                uint32_t wm0 = wm_s + ((lane & 15) * WM_P + c0 + ((lane >> 4) << 3)) * 2;
                #pragma unroll
                for (int kk = 0; kk < 8; kk++) {
                    uint32_t b[4];
                    LDSM4T(b[0], b[1], b[2], b[3], wm0 + (kk * 16 * WM_P) * 2);
                    #pragma unroll
                    for (int mt = 0; mt < 2; mt++) {
                        MMA(acc[mt][0][0],acc[mt][0][1],acc[mt][0][2],acc[mt][0][3],
                            af2[mt][kk][0],af2[mt][kk][1],af2[mt][kk][2],af2[mt][kk][3],
                            b[0], b[1]);
                        MMA(acc[mt][1][0],acc[mt][1][1],acc[mt][1][2],acc[mt][1][3],
                            af2[mt][kk][0],af2[mt][kk][1],af2[mt][kk][2],af2[mt][kk][3],
                            b[2], b[3]);
                    }
                }
                #pragma unroll
                for (int mt = 0; mt < 2; mt++) {
                    const int r0 = wrow + mt * 16 + (lane >> 2);
                    #pragma unroll
                    for (int nt = 0; nt < 2; nt++) {
                        int col = c0 + nt * 8 + ((lane & 3) << 1);
                        if (r0 < PW)
                            *reinterpret_cast<float2*>(obase + r0 * DD + col) =
                                make_float2(acc[mt][nt][0], acc[mt][nt][1]);
                        if (r0 + 8 < PW)
                            *reinterpret_cast<float2*>(obase + (r0 + 8) * DD + col) =
                                make_float2(acc[mt][nt][2], acc[mt][nt][3]);
                    }
                }
            }
        }
    }
}

extern "C" void kernel_launch(void* const* d_in, const int* in_sizes, int n_in,
                              void* d_out, int out_size)
{
    const float* x      = (const float*)d_in[0];
    const float* Wqkv   = (const float*)d_in[1];
    const float* bqkv   = (const float*)d_in[2];
    const float* Wmerge = (const float*)d_in[3];
    const float* bmerge = (const float*)d_in[4];
    const float* table  = (const float*)d_in[5];
    float* out = (float*)d_out;

    const int nwin = in_sizes[0] / (PW * DD);   // 16384

    prep_bias_kernel<<<43, 256>>>(table);

    int sms = 148;
    cudaDeviceGetAttribute(&sms, cudaDevAttrMultiProcessorCount, 0);

    cudaFuncSetAttribute(rpmha_dual6_kernel,
                         cudaFuncAttributeMaxDynamicSharedMemorySize, SMEM_BYTES);
    rpmha_dual6_kernel<<<sms, 512, SMEM_BYTES>>>(x, Wqkv, bqkv, Wmerge, bmerge,
                                                 out, nwin);
}